// round 2
// baseline (speedup 1.0000x reference)
#include <cuda_runtime.h>
#include <cuda_bf16.h>

// KANStressPredictor: elementwise map over [B, T, 3] f32 strain.
// Per group (s0, s1, s2):
//   c00 = 2*s0+1, c11 = 2*s1+1, c01 = s2
//   det = c00*c11 - c01^2 ;  L = log2(det) ;  log_J = 0.5*ln2*L
//   mean = 0.5*(c00+c11) ;  rad = sqrt(0.25*(c00-c11)^2 + c01^2)
//   out_i = exp2( ki0*(0.5*log2(lam_i) - L/6) ), lam = mean -/+ rad
//   out_2 = log_J * ki1 = 0.5*ln2*ki1 * L
//
// R2: SMEM-staged for fully coalesced global access. Round-1 profile showed
// the stride-48B per-lane pattern cost 12 lines per warp LDG (L1=63%,
// DRAM stuck at 55%). Now: coalesced float4 ldg/stg (4 lines/request),
// stride-3 group gather done via conflict-free LDS.128 in shared memory.

#define LN2_F 0.6931471805599453f

__device__ __forceinline__ void kan_group(float s0, float s1, float s2,
                                          float ki0h, float ki0_6, float k1s,
                                          float& o0, float& o1, float& o2) {
    float c00 = fmaf(2.0f, s0, 1.0f);
    float c11 = fmaf(2.0f, s1, 1.0f);
    float c01 = s2;

    float det  = fmaf(c00, c11, -c01 * c01);
    float L    = __log2f(det);                 // log2(det)

    float mean = 0.5f * (c00 + c11);
    float diff = 0.5f * (c00 - c11);
    float rad  = __fsqrt_rn(fmaf(diff, diff, c01 * c01));

    float lam0 = mean - rad;
    float lam1 = mean + rad;

    float base = ki0_6 * L;                    // ki0 * L / 6
    o0 = exp2f(fmaf(ki0h, __log2f(lam0), -base));
    o1 = exp2f(fmaf(ki0h, __log2f(lam1), -base));
    o2 = k1s * L;
}

// 256 threads/block, 4 groups/thread -> 1024 groups = 3072 floats = 768 float4
__global__ void __launch_bounds__(256)
kan_stress_smem_kernel(const float4* __restrict__ in, float4* __restrict__ out,
                       const float* __restrict__ ki0p, const float* __restrict__ ki1p) {
    __shared__ float4 s_in[768];
    __shared__ float4 s_out[768];

    int tid = threadIdx.x;
    long long gbase = (long long)blockIdx.x * 768;

    // coalesced global -> smem (lane-stride-1 float4, 4 lines per warp request)
    s_in[tid      ] = in[gbase + tid      ];
    s_in[tid + 256] = in[gbase + tid + 256];
    s_in[tid + 512] = in[gbase + tid + 512];

    float ki0 = __ldg(ki0p);
    float ki1 = __ldg(ki1p);
    float ki0h  = 0.5f * ki0;
    float ki0_6 = ki0 * (1.0f / 6.0f);
    float k1s   = 0.5f * LN2_F * ki1;

    __syncthreads();

    // stride-3 float4 gather in smem: conflict-free (48*t mod 128 covers
    // 8 distinct 16B chunks per 8-lane phase)
    float4 a = s_in[3 * tid + 0];
    float4 b = s_in[3 * tid + 1];
    float4 c = s_in[3 * tid + 2];

    float4 ra, rb, rc;
    kan_group(a.x, a.y, a.z, ki0h, ki0_6, k1s, ra.x, ra.y, ra.z);
    kan_group(a.w, b.x, b.y, ki0h, ki0_6, k1s, ra.w, rb.x, rb.y);
    kan_group(b.z, b.w, c.x, ki0h, ki0_6, k1s, rb.z, rb.w, rc.x);
    kan_group(c.y, c.z, c.w, ki0h, ki0_6, k1s, rc.y, rc.z, rc.w);

    s_out[3 * tid + 0] = ra;
    s_out[3 * tid + 1] = rb;
    s_out[3 * tid + 2] = rc;

    __syncthreads();

    // coalesced smem -> global
    out[gbase + tid      ] = s_out[tid      ];
    out[gbase + tid + 256] = s_out[tid + 256];
    out[gbase + tid + 512] = s_out[tid + 512];
}

// Scalar fallback for shapes not divisible by 1024 groups (defensive; unused
// for the benchmarked 4096x2048x3 shape).
__global__ void kan_stress_tail_kernel(const float* __restrict__ in, float* __restrict__ out,
                                       const float* __restrict__ ki0p, const float* __restrict__ ki1p,
                                       long long g0, long long n_groups) {
    long long g = g0 + blockIdx.x * (long long)blockDim.x + threadIdx.x;
    if (g >= n_groups) return;

    float ki0 = __ldg(ki0p);
    float ki1 = __ldg(ki1p);
    float ki0h  = 0.5f * ki0;
    float ki0_6 = ki0 * (1.0f / 6.0f);
    float k1s   = 0.5f * LN2_F * ki1;

    float s0 = in[3 * g + 0];
    float s1 = in[3 * g + 1];
    float s2 = in[3 * g + 2];
    float o0, o1, o2;
    kan_group(s0, s1, s2, ki0h, ki0_6, k1s, o0, o1, o2);
    out[3 * g + 0] = o0;
    out[3 * g + 1] = o1;
    out[3 * g + 2] = o2;
}

extern "C" void kernel_launch(void* const* d_in, const int* in_sizes, int n_in,
                              void* d_out, int out_size) {
    const float* strain = (const float*)d_in[0];
    const float* ki0    = (const float*)d_in[1];
    const float* ki1    = (const float*)d_in[2];
    float* out          = (float*)d_out;

    long long total_floats = in_sizes[0];
    long long n_groups = total_floats / 3;

    long long full_blocks = n_groups / 1024;   // 1024 groups per block
    if (full_blocks > 0) {
        kan_stress_smem_kernel<<<(int)full_blocks, 256>>>(
            (const float4*)strain, (float4*)out, ki0, ki1);
    }
    long long done = full_blocks * 1024;
    long long rem = n_groups - done;
    if (rem > 0) {
        int block = 256;
        int grid = (int)((rem + block - 1) / block);
        kan_stress_tail_kernel<<<grid, block>>>(strain, out, ki0, ki1, done, n_groups);
    }
}